// round 11
// baseline (speedup 1.0000x reference)
#include <cuda_runtime.h>
#include <cstdint>

#define BATCH 16
#define CH    256
#define HW    64
#define NPIX  (HW * HW)
#define STAGES 12         // 3 groups x 4 channels

typedef unsigned long long u64;

__device__ __forceinline__ u64 pk2(float lo, float hi) {
    u64 r;
    asm("mov.b64 %0, {%1, %2};" : "=l"(r) : "f"(lo), "f"(hi));
    return r;
}
__device__ __forceinline__ void upk2(u64 v, float &lo, float &hi) {
    asm("mov.b64 {%0, %1}, %2;" : "=f"(lo), "=f"(hi) : "l"(v));
}
__device__ __forceinline__ void ffma2(u64 &d, u64 a, u64 b) {
    asm("fma.rn.f32x2 %0, %1, %2, %0;" : "+l"(d) : "l"(a), "l"(b));
}
__device__ __forceinline__ void cp16z(uint32_t dst, const float* src, int srcsz) {
    asm volatile("cp.async.cg.shared.global [%0], [%1], 16, %2;"
                 :: "r"(dst), "l"(src), "r"(srcsz));
}
__device__ __forceinline__ void cp_commit() {
    asm volatile("cp.async.commit_group;");
}

// slot permutation: data chunk c (0..15) -> slot 1+c+(c>>3) in {1..8,10..17};
// slot 9 = shared zero guard (window chunk -1 and 16). Conflict-free per
// quarter-warp for every access class (verified by enumeration mod 8).
#define SLOT(c) (1 + (c) + ((c) >> 3))

// out[b, oi*9+oj, i, j] = (1/C) * sum_c x[b,c,i,j] * y[b,c,i+oi-4, j+oj-4]
// Block: 288 thr = 9 warps (warp = oi), covers b, output rows i0..i0+3.
// smem ring: STAGES x 16 rows (12 y rows i0-4..i0+7, 4 x rows i0..i0+3) x 18 slots.
// 4 channels per wait_group+__syncthreads; refill group is 2 groups ahead
// (ring of 3 groups) so refilled stages were consumed >= 1 barrier ago.
__global__ __launch_bounds__(288, 2)
void corr_kernel(const float* __restrict__ x, const float* __restrict__ y,
                 float* __restrict__ out) {
    __shared__ float4 sm[STAGES][16][18];

    const int tid = threadIdx.x;
    const int b   = blockIdx.y;
    const int i0  = blockIdx.x * 4;

    // zero the shared guard slot (slot 9) in all stages/rows
    for (int t = tid; t < STAGES * 16; t += 288)
        sm[t >> 4][t & 15][9] = make_float4(0.f, 0.f, 0.f, 0.f);

    // ---- cooperative loader setup (one 16B chunk per thread, tid < 256) ----
    const bool isload = tid < 256;
    const int  lrow = (tid >> 4) & 15;    // local row 0..15
    const int  lck  = tid & 15;           // data chunk 0..15
    const bool isx  = lrow >= 12;
    int grow = isx ? (i0 + lrow - 12) : (i0 - 4 + lrow);
    const bool valid = isx || ((unsigned)grow < (unsigned)HW);
    if (!valid) grow = 0;
    const float* gsrc = (isx ? x : y) + (size_t)b * CH * NPIX + grow * HW + lck * 4;
    const int srcsz = valid ? 16 : 0;
    const uint32_t stage_b = 16 * 18 * 16;     // bytes per stage
    const uint32_t sdst =
        (uint32_t)__cvta_generic_to_shared(&sm[0][lrow][SLOT(lck)]);

    // ---- prologue: groups 0,1 (channels 0..7) ----
    #pragma unroll
    for (int g = 0; g < 2; ++g) {
        if (isload) {
            #pragma unroll
            for (int q = 0; q < 4; ++q)
                cp16z(sdst + (uint32_t)(4 * g + q) * stage_b,
                      gsrc + (size_t)(4 * g + q) * NPIX, srcsz);
        }
        cp_commit();
    }

    // ---- compute-lane constants ----
    const int lane = tid & 31;
    const int jg   = lane & 7;        // j0 = 8*jg
    const int ro   = lane >> 3;       // output row i0+ro
    const int oi   = tid >> 5;        // 0..8
    const int srow = ro + oi;         // y row in smem (0..11)
    const int yc0  = (jg == 0) ? 9 : SLOT(2 * jg - 1);
    const int yc1  = SLOT(2 * jg);
    const int yc2  = SLOT(2 * jg + 1);
    const int yc3  = (jg == 7) ? 9 : SLOT(2 * jg + 2);
    const int xrow = 12 + ro;

    u64 aE[5][4], aO[4][4];
    #pragma unroll
    for (int e = 0; e < 5; ++e)
        #pragma unroll
        for (int t = 0; t < 4; ++t) aE[e][t] = 0ull;
    #pragma unroll
    for (int o = 0; o < 4; ++o)
        #pragma unroll
        for (int t = 0; t < 4; ++t) aO[o][t] = 0ull;

#define COMPUTE_CH(st)                                                         \
    {                                                                          \
        const float4 v0  = sm[st][srow][yc0];                                  \
        const float4 v1  = sm[st][srow][yc1];                                  \
        const float4 v2  = sm[st][srow][yc2];                                  \
        const float4 v3  = sm[st][srow][yc3];                                  \
        const float4 xv0 = sm[st][xrow][yc1];                                  \
        const float4 xv1 = sm[st][xrow][yc2];                                  \
        u64 X[4];                                                              \
        X[0] = pk2(xv0.x, xv0.y); X[1] = pk2(xv0.z, xv0.w);                    \
        X[2] = pk2(xv1.x, xv1.y); X[3] = pk2(xv1.z, xv1.w);                    \
        u64 E[8];                                                              \
        E[0] = pk2(v0.x, v0.y); E[1] = pk2(v0.z, v0.w);                        \
        E[2] = pk2(v1.x, v1.y); E[3] = pk2(v1.z, v1.w);                        \
        E[4] = pk2(v2.x, v2.y); E[5] = pk2(v2.z, v2.w);                        \
        E[6] = pk2(v3.x, v3.y); E[7] = pk2(v3.z, v3.w);                        \
        u64 O[7];                                                              \
        O[0] = pk2(v0.y, v0.z); O[1] = pk2(v0.w, v1.x);                        \
        O[2] = pk2(v1.y, v1.z); O[3] = pk2(v1.w, v2.x);                        \
        O[4] = pk2(v2.y, v2.z); O[5] = pk2(v2.w, v3.x);                        \
        O[6] = pk2(v3.y, v3.z);                                                \
        _Pragma("unroll")                                                      \
        for (int e = 0; e < 5; ++e)                                            \
            _Pragma("unroll")                                                  \
            for (int t = 0; t < 4; ++t) ffma2(aE[e][t], X[t], E[e + t]);       \
        _Pragma("unroll")                                                      \
        for (int o = 0; o < 4; ++o)                                            \
            _Pragma("unroll")                                                  \
            for (int t = 0; t < 4; ++t) ffma2(aO[o][t], X[t], O[o + t]);       \
    }

    const float* gpre = gsrc + (size_t)8 * NPIX;   // next channel to fetch
    int cgrp = 0;                                   // compute group 0..2
    int rgrp = 2;                                   // refill group = cgrp+2 mod 3

    #pragma unroll 1
    for (int k = 0; k < CH / 4; ++k) {
        // group k's 4 channels complete; barrier publishes to all warps
        asm volatile("cp.async.wait_group 1;" ::: "memory");
        __syncthreads();

        const int cs = cgrp * 4;
        COMPUTE_CH(cs);
        COMPUTE_CH(cs + 1);
        COMPUTE_CH(cs + 2);
        COMPUTE_CH(cs + 3);

        // refill group rgrp (channels 4k+8..4k+11); its stages were consumed
        // in iteration k-1 (all warps past that barrier) -> safe
        if (isload && (4 * k + 8 < CH)) {
            const uint32_t rb = sdst + (uint32_t)(rgrp * 4) * stage_b;
            cp16z(rb,               gpre,            srcsz);
            cp16z(rb +     stage_b, gpre +     NPIX, srcsz);
            cp16z(rb + 2 * stage_b, gpre + 2 * NPIX, srcsz);
            cp16z(rb + 3 * stage_b, gpre + 3 * NPIX, srcsz);
        }
        cp_commit();
        gpre += 4 * NPIX;
        cgrp = (cgrp == 2) ? 0 : cgrp + 1;
        rgrp = (rgrp == 2) ? 0 : rgrp + 1;
    }
#undef COMPUTE_CH

    // ---- epilogue ----
    const float sc = 1.0f / (float)CH;
    float* ob = out + (((size_t)b * 81 + (size_t)oi * 9) * HW + (i0 + ro)) * HW
                    + 8 * jg;
    #pragma unroll
    for (int e = 0; e < 5; ++e) {            // oj = 2e
        float v[8];
        #pragma unroll
        for (int t = 0; t < 4; ++t) upk2(aE[e][t], v[2 * t], v[2 * t + 1]);
        float* op = ob + (size_t)(2 * e) * NPIX;
        *(float4*)op       = make_float4(v[0] * sc, v[1] * sc, v[2] * sc, v[3] * sc);
        *(float4*)(op + 4) = make_float4(v[4] * sc, v[5] * sc, v[6] * sc, v[7] * sc);
    }
    #pragma unroll
    for (int o = 0; o < 4; ++o) {            // oj = 2o+1
        float v[8];
        #pragma unroll
        for (int t = 0; t < 4; ++t) upk2(aO[o][t], v[2 * t], v[2 * t + 1]);
        float* op = ob + (size_t)(2 * o + 1) * NPIX;
        *(float4*)op       = make_float4(v[0] * sc, v[1] * sc, v[2] * sc, v[3] * sc);
        *(float4*)(op + 4) = make_float4(v[4] * sc, v[5] * sc, v[6] * sc, v[7] * sc);
    }
}

extern "C" void kernel_launch(void* const* d_in, const int* in_sizes, int n_in,
                              void* d_out, int out_size) {
    const float* x = (const float*)d_in[0];
    const float* y = (const float*)d_in[1];
    float* out = (float*)d_out;
    dim3 grid(HW / 4, BATCH);   // 16 row-groups x 16 batches = 256 blocks
    corr_kernel<<<grid, 288>>>(x, y, out);
}

// round 12
// speedup vs baseline: 1.2943x; 1.2943x over previous
#include <cuda_runtime.h>
#include <cstdint>

#define BATCH 16
#define CH    256
#define HW    64
#define NPIX  (HW * HW)
#define STAGES 8          // ring depth (4 groups x 2 channels)

typedef unsigned long long u64;

union F4U { float4 f; ulonglong2 u; };

__device__ __forceinline__ u64 pk2(float lo, float hi) {
    u64 r;
    asm("mov.b64 %0, {%1, %2};" : "=l"(r) : "f"(lo), "f"(hi));
    return r;
}
__device__ __forceinline__ void upk2(u64 v, float &lo, float &hi) {
    asm("mov.b64 {%0, %1}, %2;" : "=f"(lo), "=f"(hi) : "l"(v));
}
__device__ __forceinline__ void ffma2(u64 &d, u64 a, u64 b) {
    asm("fma.rn.f32x2 %0, %1, %2, %0;" : "+l"(d) : "l"(a), "l"(b));
}
__device__ __forceinline__ void cp16z(uint32_t dst, const float* src, int srcsz) {
    asm volatile("cp.async.cg.shared.global [%0], [%1], 16, %2;"
                 :: "r"(dst), "l"(src), "r"(srcsz));
}
__device__ __forceinline__ void cp_commit() {
    asm volatile("cp.async.commit_group;");
}

// slot permutation: data chunk c (0..15) -> slot 1+c+(c>>3) in {1..8,10..17};
// slot 9 = shared zero guard (window chunk -1 and 16). Conflict-free per
// quarter-warp for every access class (verified by enumeration mod 8).
#define SLOT(c) (1 + (c) + ((c) >> 3))

// out[b, oi*9+oj, i, j] = (1/C) * sum_c x[b,c,i,j] * y[b,c,i+oi-4, j+oj-4]
// Block: 288 thr = 9 warps (warp = oi), covers b, output rows i0..i0+3.
// smem ring: STAGES x 16 rows (12 y rows i0-4..i0+7, 4 x rows i0..i0+3) x 18 slots.
// Round-8 pipeline shape (2 ch/group, wait_group 2 -> ~6 channels in flight).
// Even-aligned f32x2 operands come straight from the LDS.128 register pairs
// (union bit-cast, zero MOVs); only the 7 odd-aligned y pairs are packed.
__global__ __launch_bounds__(288, 2)
void corr_kernel(const float* __restrict__ x, const float* __restrict__ y,
                 float* __restrict__ out) {
    __shared__ float4 sm[STAGES][16][18];

    const int tid = threadIdx.x;
    const int b   = blockIdx.y;
    const int i0  = blockIdx.x * 4;

    // zero the shared guard slot (slot 9) in all stages/rows
    if (tid < 128) sm[tid >> 4][tid & 15][9] = make_float4(0.f, 0.f, 0.f, 0.f);

    // ---- cooperative loader setup (one 16B chunk per thread, tid < 256) ----
    const bool isload = tid < 256;
    const int  lrow = (tid >> 4) & 15;    // local row 0..15
    const int  lck  = tid & 15;           // data chunk 0..15
    const bool isx  = lrow >= 12;
    int grow = isx ? (i0 + lrow - 12) : (i0 - 4 + lrow);
    const bool valid = isx || ((unsigned)grow < (unsigned)HW);
    if (!valid) grow = 0;
    const float* gsrc = (isx ? x : y) + (size_t)b * CH * NPIX + grow * HW + lck * 4;
    const int srcsz = valid ? 16 : 0;
    const uint32_t stage_b = 16 * 18 * 16;     // bytes per stage
    const uint32_t sdst =
        (uint32_t)__cvta_generic_to_shared(&sm[0][lrow][SLOT(lck)]);

    // ---- prologue: 3 groups x 2 channels (ch 0..5 in flight) ----
    #pragma unroll
    for (int g = 0; g < 3; ++g) {
        if (isload) {
            cp16z(sdst + (uint32_t)(2 * g)     * stage_b, gsrc + (size_t)(2 * g)     * NPIX, srcsz);
            cp16z(sdst + (uint32_t)(2 * g + 1) * stage_b, gsrc + (size_t)(2 * g + 1) * NPIX, srcsz);
        }
        cp_commit();
    }

    // ---- compute-lane constants ----
    const int lane = tid & 31;
    const int jg   = lane & 7;        // j0 = 8*jg
    const int ro   = lane >> 3;       // output row i0+ro
    const int oi   = tid >> 5;        // 0..8
    const int srow = ro + oi;         // y row in smem (0..11)
    const int yc0  = (jg == 0) ? 9 : SLOT(2 * jg - 1);
    const int yc1  = SLOT(2 * jg);
    const int yc2  = SLOT(2 * jg + 1);
    const int yc3  = (jg == 7) ? 9 : SLOT(2 * jg + 2);
    const int xrow = 12 + ro;

    u64 aE[5][4], aO[4][4];
    #pragma unroll
    for (int e = 0; e < 5; ++e)
        #pragma unroll
        for (int t = 0; t < 4; ++t) aE[e][t] = 0ull;
    #pragma unroll
    for (int o = 0; o < 4; ++o)
        #pragma unroll
        for (int t = 0; t < 4; ++t) aO[o][t] = 0ull;

#define COMPUTE_CH(st)                                                         \
    {                                                                          \
        F4U w0, w1, w2, w3, xa, xb;                                            \
        w0.f = sm[st][srow][yc0];                                              \
        w1.f = sm[st][srow][yc1];                                              \
        w2.f = sm[st][srow][yc2];                                              \
        w3.f = sm[st][srow][yc3];                                              \
        xa.f = sm[st][xrow][yc1];                                              \
        xb.f = sm[st][xrow][yc2];                                              \
        u64 X[4];   /* register-pair aliases: no MOVs */                       \
        X[0] = xa.u.x; X[1] = xa.u.y; X[2] = xb.u.x; X[3] = xb.u.y;            \
        u64 E[8];                                                              \
        E[0] = w0.u.x; E[1] = w0.u.y; E[2] = w1.u.x; E[3] = w1.u.y;            \
        E[4] = w2.u.x; E[5] = w2.u.y; E[6] = w3.u.x; E[7] = w3.u.y;            \
        u64 O[7];   /* odd-aligned: genuine re-packs */                        \
        O[0] = pk2(w0.f.y, w0.f.z); O[1] = pk2(w0.f.w, w1.f.x);                \
        O[2] = pk2(w1.f.y, w1.f.z); O[3] = pk2(w1.f.w, w2.f.x);                \
        O[4] = pk2(w2.f.y, w2.f.z); O[5] = pk2(w2.f.w, w3.f.x);                \
        O[6] = pk2(w3.f.y, w3.f.z);                                            \
        _Pragma("unroll")                                                      \
        for (int e = 0; e < 5; ++e)                                            \
            _Pragma("unroll")                                                  \
            for (int t = 0; t < 4; ++t) ffma2(aE[e][t], X[t], E[e + t]);       \
        _Pragma("unroll")                                                      \
        for (int o = 0; o < 4; ++o)                                            \
            _Pragma("unroll")                                                  \
            for (int t = 0; t < 4; ++t) ffma2(aO[o][t], X[t], O[o + t]);       \
    }

    const float* gpre = gsrc + (size_t)6 * NPIX;

    #pragma unroll 1
    for (int k = 0; k < CH / 2; ++k) {
        // group k (channels 2k, 2k+1) complete; barrier publishes to all warps
        asm volatile("cp.async.wait_group 2;" ::: "memory");
        __syncthreads();

        const int st0 = (2 * k) & (STAGES - 1);
        COMPUTE_CH(st0);
        COMPUTE_CH(st0 + 1);          // (2k+1)&7 == st0+1 (st0 is even)

        // refill stages (2k+6)&7, (2k+7)&7 (consumed in iter k-1; safe)
        if (isload && (2 * k + 6 < CH)) {
            cp16z(sdst + (uint32_t)((2 * k + 6) & (STAGES - 1)) * stage_b, gpre, srcsz);
            cp16z(sdst + (uint32_t)((2 * k + 7) & (STAGES - 1)) * stage_b, gpre + NPIX, srcsz);
        }
        cp_commit();
        gpre += 2 * NPIX;
    }
#undef COMPUTE_CH

    // ---- epilogue ----
    const float sc = 1.0f / (float)CH;
    float* ob = out + (((size_t)b * 81 + (size_t)oi * 9) * HW + (i0 + ro)) * HW
                    + 8 * jg;
    #pragma unroll
    for (int e = 0; e < 5; ++e) {            // oj = 2e
        float v[8];
        #pragma unroll
        for (int t = 0; t < 4; ++t) upk2(aE[e][t], v[2 * t], v[2 * t + 1]);
        float* op = ob + (size_t)(2 * e) * NPIX;
        *(float4*)op       = make_float4(v[0] * sc, v[1] * sc, v[2] * sc, v[3] * sc);
        *(float4*)(op + 4) = make_float4(v[4] * sc, v[5] * sc, v[6] * sc, v[7] * sc);
    }
    #pragma unroll
    for (int o = 0; o < 4; ++o) {            // oj = 2o+1
        float v[8];
        #pragma unroll
        for (int t = 0; t < 4; ++t) upk2(aO[o][t], v[2 * t], v[2 * t + 1]);
        float* op = ob + (size_t)(2 * o + 1) * NPIX;
        *(float4*)op       = make_float4(v[0] * sc, v[1] * sc, v[2] * sc, v[3] * sc);
        *(float4*)(op + 4) = make_float4(v[4] * sc, v[5] * sc, v[6] * sc, v[7] * sc);
    }
}

extern "C" void kernel_launch(void* const* d_in, const int* in_sizes, int n_in,
                              void* d_out, int out_size) {
    const float* x = (const float*)d_in[0];
    const float* y = (const float*)d_in[1];
    float* out = (float*)d_out;
    dim3 grid(HW / 4, BATCH);   // 16 row-groups x 16 batches = 256 blocks
    corr_kernel<<<grid, 288>>>(x, y, out);
}